// round 4
// baseline (speedup 1.0000x reference)
#include <cuda_runtime.h>
#include <cstdint>

// ---------------------------------------------------------------------------
// Problem dims
// ---------------------------------------------------------------------------
#define BB   8192
#define KTOT 19000
#define SD   256
#define PDD  128
#define PP   16
#define DD   64

// GEMM tiling
#define BM 64
#define BN 256
#define BK 32
#define NSLICE 8
#define KSLICE_LEN 2376          // slices 0..6 (slice 7 = 2368 = 19000-7*2376)
#define MTILES (BB / BM)         // 128
#define NUNITS (MTILES * NSLICE) // 1024
#define GRID_GEMM 148

#define A_STRIDE 36              // floats; bank-conflict-free A frag reads
#define B_STRIDE 264             // floats; bank-conflict-free B frag reads
#define STAGE_A_BYTES (BM * A_STRIDE * 4)       // 9216
#define STAGE_B_BYTES (BK * B_STRIDE * 4)       // 33792
#define STAGE_BYTES   (STAGE_A_BYTES + STAGE_B_BYTES)  // 43008
#define SMEM_GEMM     (3 * STAGE_BYTES)         // 129024

// pathway grouping
#define CHUNK  64
#define NCHUNK 24
#define SMEM_PW (SD * PDD * 4 + SD * 4 + 64)    // Wp tile + h row + red

// ---------------------------------------------------------------------------
// Device globals (no allocations allowed)
// ---------------------------------------------------------------------------
__device__ float g_w1r[(size_t)KTOT * SD];          // tf32-rounded W1 (same layout)
__device__ float g_hp[NSLICE][(size_t)BB * SD];     // split-K partial h (bias in slice 0)
__device__ int   g_cnt[PP], g_off[PP], g_cur[PP];
__device__ int   g_ord[BB];

// ---------------------------------------------------------------------------
// helpers
// ---------------------------------------------------------------------------
__device__ __forceinline__ uint32_t smem_u32(const void* p) {
    uint32_t a;
    asm("{ .reg .u64 t; cvta.to.shared.u64 t, %1; cvt.u32.u64 %0, t; }" : "=r"(a) : "l"(p));
    return a;
}
__device__ __forceinline__ uint32_t cvt_tf32(float f) {
    uint32_t r;
    asm("cvt.rn.tf32.f32 %0, %1;" : "=r"(r) : "f"(f));
    return r;
}
__device__ __forceinline__ void cp_async16(uint32_t dst, const void* src, bool valid) {
    int sz = valid ? 16 : 0;   // sz<16 zero-fills the remainder
    asm volatile("cp.async.cg.shared.global [%0], [%1], 16, %2;\n"
                 :: "r"(dst), "l"(src), "r"(sz));
}
#define CP_COMMIT() asm volatile("cp.async.commit_group;" ::: "memory")
#define CP_WAIT1()  asm volatile("cp.async.wait_group 1;" ::: "memory")

__device__ __forceinline__ void mma_tf32(float* c, const uint32_t* a, const uint32_t* b) {
    asm volatile(
        "mma.sync.aligned.m16n8k8.row.col.f32.tf32.tf32.f32 "
        "{%0,%1,%2,%3}, {%4,%5,%6,%7}, {%8,%9}, {%0,%1,%2,%3};"
        : "+f"(c[0]), "+f"(c[1]), "+f"(c[2]), "+f"(c[3])
        : "r"(a[0]), "r"(a[1]), "r"(a[2]), "r"(a[3]), "r"(b[0]), "r"(b[1]));
}

// ---------------------------------------------------------------------------
// small kernels: sort-by-pathway machinery + W1 pre-round
// ---------------------------------------------------------------------------
__global__ void zero_cnt_kernel() {
    if (threadIdx.x < PP) g_cnt[threadIdx.x] = 0;
}

__global__ void hist_kernel(const int* __restrict__ di, const int* __restrict__ d2p) {
    __shared__ int lc[PP];
    if (threadIdx.x < PP) lc[threadIdx.x] = 0;
    __syncthreads();
    int i = blockIdx.x * 256 + threadIdx.x;
    atomicAdd(&lc[d2p[di[i]]], 1);
    __syncthreads();
    if (threadIdx.x < PP) atomicAdd(&g_cnt[threadIdx.x], lc[threadIdx.x]);
}

__global__ void scan_kernel() {
    if (threadIdx.x == 0) {
        int off = 0;
        for (int p = 0; p < PP; p++) {
            g_off[p] = off;
            g_cur[p] = off;
            off += g_cnt[p];
        }
    }
}

__global__ void scatter_kernel(const int* __restrict__ di, const int* __restrict__ d2p) {
    int i = blockIdx.x * 256 + threadIdx.x;
    int p = d2p[di[i]];
    int pos = atomicAdd(&g_cur[p], 1);
    g_ord[pos] = i;
}

__global__ void preround_w1_kernel(const float* __restrict__ W1) {
    int i = blockIdx.x * 256 + threadIdx.x;       // float4 index; 1216000 total
    float4 v = ((const float4*)W1)[i];
    uint4 w;
    w.x = cvt_tf32(v.x); w.y = cvt_tf32(v.y);
    w.z = cvt_tf32(v.z); w.w = cvt_tf32(v.w);
    ((uint4*)g_w1r)[i] = w;
}

// ---------------------------------------------------------------------------
// GEMM: persistent 148-CTA, BM=64 x BN=256, split-K=8, tf32 mma.sync.
// 256 threads = 8 warps, warp grid 2(m) x 4(n), warp tile 32x64.
// ---------------------------------------------------------------------------
#define LOAD_FRAGS(As, Bs, ks, a, b) do {                                      \
    const int _c  = (ks) * 8 + (lane & 3);                                     \
    _Pragma("unroll")                                                          \
    for (int mi = 0; mi < 2; mi++) {                                           \
        const int _r = wrow + mi * 16 + (lane >> 2);                           \
        a[mi][0] = cvt_tf32((As)[(_r    ) * A_STRIDE + _c    ]);               \
        a[mi][1] = cvt_tf32((As)[(_r + 8) * A_STRIDE + _c    ]);               \
        a[mi][2] = cvt_tf32((As)[(_r    ) * A_STRIDE + _c + 4]);               \
        a[mi][3] = cvt_tf32((As)[(_r + 8) * A_STRIDE + _c + 4]);               \
    }                                                                          \
    const int _kr = (ks) * 8 + (lane & 3);                                     \
    _Pragma("unroll")                                                          \
    for (int ni = 0; ni < 8; ni++) {                                           \
        const int _cc = wcol + ni * 8 + (lane >> 2);                           \
        b[ni][0] = __float_as_uint((Bs)[(_kr    ) * B_STRIDE + _cc]);          \
        b[ni][1] = __float_as_uint((Bs)[(_kr + 4) * B_STRIDE + _cc]);          \
    }                                                                          \
} while (0)

__global__ __launch_bounds__(256, 1)
void gemm_tf32_kernel(const float* __restrict__ x, const float* __restrict__ b1)
{
    extern __shared__ char smem[];
    const uint32_t sb = smem_u32(smem);

    const int tid  = threadIdx.x;
    const int lane = tid & 31;
    const int wid  = tid >> 5;
    const int wm   = wid & 1;
    const int wn   = wid >> 1;
    const int wrow = wm * 32;
    const int wcol = wn * 64;

    for (int u = blockIdx.x; u < NUNITS; u += GRID_GEMM) {
        const int m0     = (u >> 3) * BM;
        const int ksl    = u & 7;
        const int kstart = ksl * KSLICE_LEN;
        const int klen   = (ksl < 7) ? KSLICE_LEN : (KTOT - 7 * KSLICE_LEN);
        const int kend   = kstart + klen;
        const int ntiles = (klen + BK - 1) / BK;   // 75 or 74

        float acc[2][8][4];
#pragma unroll
        for (int mi = 0; mi < 2; mi++)
#pragma unroll
            for (int ni = 0; ni < 8; ni++)
#pragma unroll
                for (int j = 0; j < 4; j++) acc[mi][ni][j] = 0.f;

        __syncthreads();   // previous unit fully done with smem stages

        auto load_tile = [&](int kb, int stage) {
            const uint32_t ab  = sb + stage * STAGE_BYTES;
            const uint32_t bbs = ab + STAGE_A_BYTES;
#pragma unroll
            for (int i = 0; i < 2; i++) {
                int seg = tid + i * 256;            // 0..511
                int row = seg >> 3;                 // 0..63
                int ks  = (seg & 7) << 2;           // 0..28
                int kg  = kb + ks;
                cp_async16(ab + row * (A_STRIDE * 4) + ks * 4,
                           x + (size_t)(m0 + row) * KTOT + kg, kg < kend);
            }
#pragma unroll
            for (int i = 0; i < 8; i++) {
                int seg = tid + i * 256;            // 0..2047
                int row = seg >> 6;                 // 0..31
                int ns  = (seg & 63) << 2;          // 0..252
                int kg  = kb + row;
                cp_async16(bbs + row * (B_STRIDE * 4) + ns * 4,
                           g_w1r + (size_t)kg * SD + ns, kg < kend);
            }
        };

        load_tile(kstart,      0); CP_COMMIT();
        load_tile(kstart + BK, 1); CP_COMMIT();

        for (int t = 0; t < ntiles; t++) {
            CP_WAIT1();
            __syncthreads();

            if (t + 2 < ntiles) load_tile(kstart + (t + 2) * BK, (t + 2) % 3);
            CP_COMMIT();

            const float* As = (const float*)(smem + (t % 3) * STAGE_BYTES);
            const float* Bs = (const float*)(smem + (t % 3) * STAGE_BYTES + STAGE_A_BYTES);

            uint32_t af[2][2][4], bf[2][8][2];
            LOAD_FRAGS(As, Bs, 0, af[0], bf[0]);
#pragma unroll
            for (int ks = 0; ks < 4; ks++) {
                const int cur = ks & 1;
                if (ks < 3) {
                    const int nxt = cur ^ 1;
                    LOAD_FRAGS(As, Bs, ks + 1, af[nxt], bf[nxt]);
                }
#pragma unroll
                for (int mi = 0; mi < 2; mi++)
#pragma unroll
                    for (int ni = 0; ni < 8; ni++)
                        mma_tf32(acc[mi][ni], af[cur][mi], bf[cur][ni]);
            }
            __syncthreads();   // stage reused by load at t+1
        }

        // epilogue: partial h for this k-slice (bias folded into slice 0)
        float* op = g_hp[ksl];
#pragma unroll
        for (int mi = 0; mi < 2; mi++) {
            int r0 = m0 + wrow + mi * 16 + (lane >> 2);
#pragma unroll
            for (int ni = 0; ni < 8; ni++) {
                int c = wcol + ni * 8 + (lane & 3) * 2;
                float bx = 0.f, by = 0.f;
                if (ksl == 0) { bx = __ldg(&b1[c]); by = __ldg(&b1[c + 1]); }
                float2 v0 = make_float2(acc[mi][ni][0] + bx, acc[mi][ni][1] + by);
                float2 v1 = make_float2(acc[mi][ni][2] + bx, acc[mi][ni][3] + by);
                *(float2*)(op + (size_t)r0 * SD + c)       = v0;
                *(float2*)(op + (size_t)(r0 + 8) * SD + c) = v1;
            }
        }
    }
}

// ---------------------------------------------------------------------------
// Grouped pathway kernel: block = (pathway p, 64-sample chunk).
// Wp[p] cached fully in smem (128 KB). Thread t owns output column t.
// ---------------------------------------------------------------------------
__global__ __launch_bounds__(128)
void pathway_grouped_kernel(const float* __restrict__ Wp,
                            const float* __restrict__ bp,
                            const float* __restrict__ Wd,
                            const float* __restrict__ bd,
                            const int*   __restrict__ di,
                            float*       __restrict__ out)
{
    extern __shared__ float sm[];
    float* wps = sm;                 // [SD][PDD]
    float* hs  = sm + SD * PDD;      // [SD]
    float* red = hs + SD;            // [4]

    const int p    = blockIdx.x;
    const int base = blockIdx.y * CHUNK;
    const int cnt  = g_cnt[p];
    if (base >= cnt) return;

    const int t = threadIdx.x;

    // load Wp[p] -> smem (32768 floats = 8192 float4)
    const float4* wsrc = (const float4*)(Wp + (size_t)p * SD * PDD);
    float4* wdst = (float4*)wps;
#pragma unroll
    for (int i = 0; i < 64; i++) wdst[t + i * 128] = wsrc[t + i * 128];

    const float bpv   = bp[p * PDD + t];
    const int   nloc  = min(CHUNK, cnt - base);
    const int   obase = g_off[p] + base;
    __syncthreads();

    for (int j = 0; j < nloc; j++) {
        const int sample = g_ord[obase + j];

        float h0 = 0.f, h1 = 0.f;
#pragma unroll
        for (int q = 0; q < NSLICE; q++) {
            h0 += g_hp[q][(size_t)sample * SD + t];
            h1 += g_hp[q][(size_t)sample * SD + t + 128];
        }
        hs[t]       = fmaxf(h0, 0.f);
        hs[t + 128] = fmaxf(h1, 0.f);
        __syncthreads();

        float acc = bpv;
#pragma unroll 8
        for (int s = 0; s < SD; s++)
            acc = fmaf(hs[s], wps[s * PDD + t], acc);
        acc = fmaxf(acc, 0.f);

        const int drug = di[sample];
        float v = acc * Wd[drug * PDD + t];
#pragma unroll
        for (int off = 16; off > 0; off >>= 1)
            v += __shfl_xor_sync(0xffffffffu, v, off);
        if ((t & 31) == 0) red[t >> 5] = v;
        __syncthreads();
        if (t == 0)
            out[sample] = red[0] + red[1] + red[2] + red[3] + bd[drug];
        __syncthreads();   // hs/red reuse next iteration
    }
}

// ---------------------------------------------------------------------------
// Launch. Inputs: x, drug_indices, W1, b1, Wp, bp, Wd, bd, drug_to_pw
// ---------------------------------------------------------------------------
extern "C" void kernel_launch(void* const* d_in, const int* in_sizes, int n_in,
                              void* d_out, int out_size)
{
    const float* x            = (const float*)d_in[0];
    const int*   drug_indices = (const int*)  d_in[1];
    const float* W1           = (const float*)d_in[2];
    const float* b1           = (const float*)d_in[3];
    const float* Wp           = (const float*)d_in[4];
    const float* bp           = (const float*)d_in[5];
    const float* Wd           = (const float*)d_in[6];
    const float* bd           = (const float*)d_in[7];
    const int*   drug_to_pw   = (const int*)  d_in[8];
    float*       out          = (float*)d_out;

    static int attr_set = 0;
    if (!attr_set) {
        cudaFuncSetAttribute(gemm_tf32_kernel,
                             cudaFuncAttributeMaxDynamicSharedMemorySize, SMEM_GEMM);
        cudaFuncSetAttribute(pathway_grouped_kernel,
                             cudaFuncAttributeMaxDynamicSharedMemorySize, SMEM_PW);
        attr_set = 1;
    }

    // sort-by-pathway prep (independent of GEMM)
    zero_cnt_kernel<<<1, 32>>>();
    hist_kernel<<<BB / 256, 256>>>(drug_indices, drug_to_pw);
    scan_kernel<<<1, 32>>>();
    scatter_kernel<<<BB / 256, 256>>>(drug_indices, drug_to_pw);

    // W1 tf32 pre-round
    preround_w1_kernel<<<(KTOT * SD / 4) / 256, 256>>>(W1);

    // main GEMM (persistent)
    gemm_tf32_kernel<<<GRID_GEMM, 256, SMEM_GEMM>>>(x, b1);

    // grouped pathway + drug head
    pathway_grouped_kernel<<<dim3(PP, NCHUNK), 128, SMEM_PW>>>(
        Wp, bp, Wd, bd, drug_indices, out);
}